// round 13
// baseline (speedup 1.0000x reference)
#include <cuda_runtime.h>
#include <cuda_bf16.h>
#include <cstdint>

// Problem constants
#define PTOT   8192        // B*H*W points
#define NCODES 16384
#define DIM    256
#define ZELEMS 2097152     // 8*256*32*32

#define SZ 24.0f           // z int8 scale
#define SE 2.0e6f          // e int8 scale
#define INVQ (1.0f / (SZ * SE))

// Scratch (static device globals; no allocations allowed)
__device__ float          g_a[PTOT];          // sequential fp32 ||z_row||^2
__device__ int            g_idx[PTOT];
__device__ float          g_part[2048];
__device__ float          g_tmax[(size_t)PTOT * 64];       // per-row per-256-tile max
__device__ int8_t         g_e8[(size_t)NCODES * DIM];      // codebook int8 (x SE)
__device__ __nv_bfloat16  g_ybf[(size_t)PTOT * NCODES];    // 256 MB y matrix (bf16)

// ---------------------------------------------------------------------------
__device__ __forceinline__ uint32_t smem_u32(const void* p) {
    uint32_t a;
    asm("{ .reg .u64 t; cvta.to.shared.u64 t, %1; cvt.u32.u64 %0, t; }" : "=r"(a) : "l"(p));
    return a;
}
__device__ __forceinline__ void mma_s8(int c[4],
                                       uint32_t a0, uint32_t a1, uint32_t a2, uint32_t a3,
                                       uint32_t b0, uint32_t b1) {
    asm volatile(
        "mma.sync.aligned.m16n8k32.row.col.s32.s8.s8.s32 "
        "{%0,%1,%2,%3}, {%4,%5,%6,%7}, {%8,%9}, {%0,%1,%2,%3};\n"
        : "+r"(c[0]), "+r"(c[1]), "+r"(c[2]), "+r"(c[3])
        : "r"(a0), "r"(a1), "r"(a2), "r"(a3), "r"(b0), "r"(b1));
}
#define LDSM4(r0, r1, r2, r3, addr) \
    asm volatile("ldmatrix.sync.aligned.m8n8.x4.shared.b16 {%0,%1,%2,%3}, [%4];" \
        : "=r"(r0), "=r"(r1), "=r"(r2), "=r"(r3) : "r"(addr))

__device__ __forceinline__ int8_t quant_e(float v) {
    int q = __float2int_rn(v * SE);
    return (int8_t)max(-127, min(127, q));
}
__device__ __forceinline__ int8_t quant_z(float v) {
    int q = __float2int_rn(v * SZ);
    return (int8_t)max(-127, min(127, q));
}

// ---------------------------------------------------------------------------
// Kernel: e -> int8 (x SE)
// ---------------------------------------------------------------------------
__global__ void conv_e_kernel(const float* __restrict__ e) {
    size_t i = ((size_t)blockIdx.x * 256 + threadIdx.x) * 8;
    float4 v0 = *reinterpret_cast<const float4*>(e + i);
    float4 v1 = *reinterpret_cast<const float4*>(e + i + 4);
    uint32_t lo = (uint8_t)quant_e(v0.x) | ((uint8_t)quant_e(v0.y) << 8) |
                  ((uint8_t)quant_e(v0.z) << 16) | ((uint32_t)(uint8_t)quant_e(v0.w) << 24);
    uint32_t hi = (uint8_t)quant_e(v1.x) | ((uint8_t)quant_e(v1.y) << 8) |
                  ((uint8_t)quant_e(v1.z) << 16) | ((uint32_t)(uint8_t)quant_e(v1.w) << 24);
    *reinterpret_cast<uint2*>(g_e8 + i) = make_uint2(lo, hi);
}

// ---------------------------------------------------------------------------
// Kernel A: a_p = sum_c fl(z^2), strictly sequential fp32, no FMA contraction.
// ---------------------------------------------------------------------------
__global__ void a_kernel(const float* __restrict__ z) {
    int p = blockIdx.x * 256 + threadIdx.x;
    int b = p >> 10, hw = p & 1023;
    const float* zp = z + (size_t)b * (DIM * 1024) + hw;
    float acc = 0.f;
    #pragma unroll 8
    for (int c = 0; c < DIM; c++) {
        float v = zp[(size_t)c * 1024];
        acc = __fadd_rn(acc, __fmul_rn(v, v));
    }
    g_a[p] = acc;
}

// ---------------------------------------------------------------------------
// Kernel B: INT8 tensor-core GEMM  y ~ z . E^T  (selection pass, y in bf16).
// mma.sync.m16n8k32.s32.s8.s8 + ldmatrix (byte-layout identical to bf16 k16).
// Block 256 thr = 8 warps (2M x 4N). M-tile 64, N-tile 256, K=256 in
// 64-byte chunks (4 per K), double buffered with register prefetch.
// A (zs) holds full K -> k offset includes chunk base; B holds one chunk.
// ---------------------------------------------------------------------------
#define ZSB 272                  // z row stride bytes (256 + 16 pad)
#define ESB 80                   // E chunk row stride bytes (64 + 16 pad)
#define ZS_BYTES (64 * ZSB)      // 17408
#define ES_BYTES (256 * ESB)     // 20480 per buffer
#define GEMM_SMEM (ZS_BYTES + 2 * ES_BYTES)   // 58368

__global__ __launch_bounds__(256, 1)
void gemm_mma_kernel(const float* __restrict__ z) {
    extern __shared__ char smem[];
    char* zs = smem;                          // [64][ZSB]
    char* es = smem + ZS_BYTES;               // [2][256][ESB]

    const int tid  = threadIdx.x;
    const int wid  = tid >> 5, lane = tid & 31;
    const int g    = lane >> 2, tig = lane & 3;
    const int wm   = wid & 1;          // warp row block (2 x 32 rows)
    const int wn   = wid >> 1;         // warp col block (4 x 64 cols)

    const int row0 = blockIdx.x * 64;
    const int b    = row0 >> 10;
    const int hw0  = row0 & 1023;
    const float* zbase = z + (size_t)b * (DIM * 1024) + hw0;

    // Load z tile as int8: zs[r][c] = s8(z[b, c, hw0 + r] * SZ)
    for (int i = tid; i < 64 * 256; i += 256) {
        int c = i >> 6, r = i & 63;
        zs[r * ZSB + c] = quant_z(zbase[(size_t)c * 1024 + r]);
    }
    __syncthreads();

    const uint4* eg = reinterpret_cast<const uint4*>(g_e8);   // 16 uint4 per code row
    const int q  = tid & 3;            // uint4 slot within 64-byte chunk
    const int n0 = tid >> 2;           // 0..63 code group

    // ldmatrix base addresses (bytes)
    const uint32_t zs_base = smem_u32(zs);
    const uint32_t es_base = smem_u32(es);
    uint32_t aaddr[2];
    #pragma unroll
    for (int ms = 0; ms < 2; ms++)
        aaddr[ms] = zs_base +
            (wm * 32 + ms * 16 + (lane & 15)) * ZSB + ((lane >> 4) & 1) * 16;
    uint32_t baddr[4];
    #pragma unroll
    for (int j = 0; j < 4; j++)
        baddr[j] = es_base +
            (wn * 64 + j * 16 + (lane & 7) + ((lane & 16) >> 1)) * ESB +
            ((lane >> 3) & 1) * 16;

    for (int nb = 0; nb < NCODES; nb += 256) {
        int c[2][8][4];
        #pragma unroll
        for (int ms = 0; ms < 2; ms++)
            #pragma unroll
            for (int ns = 0; ns < 8; ns++)
                #pragma unroll
                for (int j = 0; j < 4; j++) c[ms][ns][j] = 0;

        // preload K-chunk 0 into buffer 0
        {
            uint4 pf[4];
            #pragma unroll
            for (int p = 0; p < 4; p++)
                pf[p] = eg[(size_t)(nb + n0 + 64 * p) * 16 + q];
            #pragma unroll
            for (int p = 0; p < 4; p++)
                *reinterpret_cast<uint4*>(es + (n0 + 64 * p) * ESB + 16 * q) = pf[p];
        }
        __syncthreads();

        #pragma unroll
        for (int kc = 0; kc < 4; kc++) {
            uint4 pf[4];
            if (kc < 3) {
                #pragma unroll
                for (int p = 0; p < 4; p++)
                    pf[p] = eg[(size_t)(nb + n0 + 64 * p) * 16 + (kc + 1) * 4 + q];
            }

            const uint32_t bufoff = (uint32_t)((kc & 1) * ES_BYTES);

            #pragma unroll
            for (int ks = 0; ks < 2; ks++) {
                const uint32_t kofs_a = (uint32_t)(kc * 64 + ks * 32);  // A: full-K tile
                const uint32_t kofs_b = (uint32_t)(ks * 32);            // B: within chunk
                uint32_t a[2][4], bfr[8][2];
                LDSM4(a[0][0], a[0][1], a[0][2], a[0][3], aaddr[0] + kofs_a);
                LDSM4(a[1][0], a[1][1], a[1][2], a[1][3], aaddr[1] + kofs_a);
                #pragma unroll
                for (int j = 0; j < 4; j++)
                    LDSM4(bfr[2 * j][0], bfr[2 * j][1], bfr[2 * j + 1][0], bfr[2 * j + 1][1],
                          baddr[j] + bufoff + kofs_b);
                #pragma unroll
                for (int ns = 0; ns < 8; ns++) {
                    mma_s8(c[0][ns], a[0][0], a[0][1], a[0][2], a[0][3],
                           bfr[ns][0], bfr[ns][1]);
                    mma_s8(c[1][ns], a[1][0], a[1][1], a[1][2], a[1][3],
                           bfr[ns][0], bfr[ns][1]);
                }
            }

            if (kc < 3) {
                char* wb = es + ((kc + 1) & 1) * ES_BYTES;
                #pragma unroll
                for (int p = 0; p < 4; p++)
                    *reinterpret_cast<uint4*>(wb + (n0 + 64 * p) * ESB + 16 * q) = pf[p];
            }
            __syncthreads();
        }

        // Epilogue: dequant -> y bf16 stores + per-thread tile max
        float rmax[4];
        #pragma unroll
        for (int i = 0; i < 4; i++) rmax[i] = -3.4e38f;

        #pragma unroll
        for (int ms = 0; ms < 2; ms++) {
            int r0 = row0 + wm * 32 + ms * 16 + g;
            #pragma unroll
            for (int ns = 0; ns < 8; ns++) {
                float y0 = (float)c[ms][ns][0] * INVQ;
                float y1 = (float)c[ms][ns][1] * INVQ;
                float y2 = (float)c[ms][ns][2] * INVQ;
                float y3 = (float)c[ms][ns][3] * INVQ;
                rmax[ms * 2]     = fmaxf(rmax[ms * 2],     fmaxf(y0, y1));
                rmax[ms * 2 + 1] = fmaxf(rmax[ms * 2 + 1], fmaxf(y2, y3));
                int col = nb + wn * 64 + ns * 8 + 2 * tig;
                __nv_bfloat162 lo(__float2bfloat16(y0), __float2bfloat16(y1));
                __nv_bfloat162 hi(__float2bfloat16(y2), __float2bfloat16(y3));
                *reinterpret_cast<__nv_bfloat162*>(&g_ybf[(size_t)r0 * NCODES + col]) = lo;
                *reinterpret_cast<__nv_bfloat162*>(&g_ybf[(size_t)(r0 + 8) * NCODES + col]) = hi;
            }
        }

        // Reduce tile max across the 16 threads per row; store g_tmax[row][tile]
        float* rm = reinterpret_cast<float*>(es);   // E buffers idle here
        #pragma unroll
        for (int ms = 0; ms < 2; ms++)
            #pragma unroll
            for (int half = 0; half < 2; half++) {
                int rl = wm * 32 + ms * 16 + g + half * 8;
                rm[rl * 16 + wn * 4 + tig] = rmax[ms * 2 + half];
            }
        __syncthreads();
        if (tid < 64) {
            float m = -3.4e38f;
            #pragma unroll
            for (int j = 0; j < 16; j++) m = fmaxf(m, rm[tid * 16 + j]);
            g_tmax[(size_t)(row0 + tid) * 64 + (nb >> 8)] = m;
        }
        __syncthreads();
    }
}

// ---------------------------------------------------------------------------
// Kernel C: tile-gated refine. rowmax from g_tmax; scan only tiles whose max
// clears rowmax - MARGIN; fp64 recompute; reference rounding; first-index ties.
// MARGIN covers d-bin 3.1e-5 + 2x int8 selection err (~8e-5) + bf16 store.
// ---------------------------------------------------------------------------
#define MARGIN 2.5e-4f
#define MAXCAND 64

__global__ void refine_kernel(const float* __restrict__ z,
                              const float* __restrict__ e) {
    __shared__ float s_z[256];
    __shared__ float s_red[256];
    __shared__ float s_tmax[64];
    __shared__ int   s_cand[MAXCAND];
    __shared__ float s_d[MAXCAND];
    __shared__ int   s_cnt;

    const int p = blockIdx.x;
    const int b = p >> 10, hw = p & 1023;
    const int t = threadIdx.x;

    s_z[t] = z[(size_t)b * (DIM * 1024) + (size_t)t * 1024 + hw];
    if (t == 0) s_cnt = 0;

    float tm = -3.4e38f;
    if (t < 64) { tm = g_tmax[(size_t)p * 64 + t]; s_tmax[t] = tm; }
    s_red[t] = tm;
    __syncthreads();
    for (int s = 128; s; s >>= 1) {
        if (t < s) s_red[t] = fmaxf(s_red[t], s_red[t + s]);
        __syncthreads();
    }
    const float thr = s_red[0] - MARGIN;

    const __nv_bfloat16* yrow = g_ybf + (size_t)p * NCODES;
    for (int tt = 0; tt < 64; tt++) {
        if (s_tmax[tt] > thr) {
            float v = __bfloat162float(yrow[tt * 256 + t]);
            if (v > thr) {
                int slot = atomicAdd(&s_cnt, 1);
                if (slot < MAXCAND) s_cand[slot] = tt * 256 + t;
            }
        }
    }
    __syncthreads();

    const int cnt = min(s_cnt, MAXCAND);
    const float a = g_a[p];
    const int wid = t >> 5, lane = t & 31;

    for (int ci = wid; ci < cnt; ci += 8) {
        const float* er = e + (size_t)s_cand[ci] * DIM;
        double acc = 0.0;
        #pragma unroll
        for (int j = 0; j < 8; j++) {
            int cc = lane + 32 * j;
            acc += (double)s_z[cc] * (double)er[cc];
        }
        #pragma unroll
        for (int mlt = 16; mlt; mlt >>= 1)
            acc += __shfl_xor_sync(0xffffffffu, acc, mlt);
        if (lane == 0) {
            float y32 = (float)acc;
            s_d[ci] = __fsub_rn(a, __fmul_rn(2.0f, y32));
        }
    }
    __syncthreads();

    if (t == 0) {
        float bd = 3.4e38f; int bn = 0x7fffffff;
        for (int ci = 0; ci < cnt; ci++) {
            float d = s_d[ci]; int n = s_cand[ci];
            if (d < bd || (d == bd && n < bn)) { bd = d; bn = n; }
        }
        g_idx[p] = bn;
    }
}

// ---------------------------------------------------------------------------
// Kernel D: gather + straight-through rounding emulation + partial loss sums.
// ---------------------------------------------------------------------------
__global__ void gather_loss_kernel(const float* __restrict__ z,
                                   const float* __restrict__ e,
                                   float* __restrict__ out) {
    __shared__ float red[256];
    float acc = 0.f;
    for (int i = blockIdx.x * 256 + threadIdx.x; i < ZELEMS; i += 2048 * 256) {
        int bidx = i >> 18;
        int c    = (i >> 10) & 255;
        int hw   = i & 1023;
        int n    = g_idx[(bidx << 10) | hw];
        float v  = e[(size_t)n * DIM + c];
        float zb = z[i];
        float d  = __fsub_rn(v, zb);
        out[i]   = __fadd_rn(zb, d);
        acc += d * d;
    }
    red[threadIdx.x] = acc;
    __syncthreads();
    for (int s = 128; s; s >>= 1) {
        if (threadIdx.x < s) red[threadIdx.x] += red[threadIdx.x + s];
        __syncthreads();
    }
    if (threadIdx.x == 0) g_part[blockIdx.x] = red[0];
}

// ---------------------------------------------------------------------------
// Kernel E: final loss. loss = (BETA + 1) * mean = 2 * sum / ZELEMS
// ---------------------------------------------------------------------------
__global__ void loss_kernel(float* __restrict__ out, int out_size) {
    __shared__ float red[256];
    float acc = 0.f;
    for (int t = threadIdx.x; t < 2048; t += 256) acc += g_part[t];
    red[threadIdx.x] = acc;
    __syncthreads();
    for (int s = 128; s; s >>= 1) {
        if (threadIdx.x < s) red[threadIdx.x] += red[threadIdx.x + s];
        __syncthreads();
    }
    if (threadIdx.x == 0 && out_size > ZELEMS)
        out[ZELEMS] = 2.0f * red[0] / (float)ZELEMS;
}

// ---------------------------------------------------------------------------
extern "C" void kernel_launch(void* const* d_in, const int* in_sizes, int n_in,
                              void* d_out, int out_size) {
    const float* z = (const float*)d_in[0];   // (8,256,32,32) f32
    const float* e = (const float*)d_in[1];   // (16384,256)   f32
    float* out = (float*)d_out;

    cudaFuncSetAttribute(gemm_mma_kernel,
                         cudaFuncAttributeMaxDynamicSharedMemorySize, GEMM_SMEM);

    conv_e_kernel<<<2048, 256>>>(e);
    a_kernel<<<PTOT / 256, 256>>>(z);
    gemm_mma_kernel<<<PTOT / 64, 256, GEMM_SMEM>>>(z);
    refine_kernel<<<PTOT, 256>>>(z, e);
    gather_loss_kernel<<<2048, 256>>>(z, e, out);
    loss_kernel<<<1, 256>>>(out, out_size);
}

// round 14
// speedup vs baseline: 1.4261x; 1.4261x over previous
#include <cuda_runtime.h>
#include <cuda_bf16.h>
#include <cstdint>

// Problem constants
#define PTOT   8192        // B*H*W points
#define NCODES 16384
#define DIM    256
#define ZELEMS 2097152     // 8*256*32*32

// Scratch (static device globals; no allocations allowed)
__device__ float          g_a[PTOT];          // sequential fp32 ||z_row||^2
__device__ int            g_idx[PTOT];
__device__ float          g_part[2048];
__device__ float          g_tmax[(size_t)PTOT * 64];       // per-row per-256-tile max
__device__ __nv_bfloat16  g_ebf[(size_t)NCODES * DIM];     // codebook bf16
__device__ __nv_bfloat16  g_ybf[(size_t)PTOT * NCODES];    // 256 MB y matrix (bf16)

// ---------------------------------------------------------------------------
__device__ __forceinline__ uint32_t smem_u32(const void* p) {
    uint32_t a;
    asm("{ .reg .u64 t; cvta.to.shared.u64 t, %1; cvt.u32.u64 %0, t; }" : "=r"(a) : "l"(p));
    return a;
}
__device__ __forceinline__ void mma_bf16(float c[4],
                                         uint32_t a0, uint32_t a1, uint32_t a2, uint32_t a3,
                                         uint32_t b0, uint32_t b1) {
    asm volatile(
        "mma.sync.aligned.m16n8k16.row.col.f32.bf16.bf16.f32 "
        "{%0,%1,%2,%3}, {%4,%5,%6,%7}, {%8,%9}, {%0,%1,%2,%3};\n"
        : "+f"(c[0]), "+f"(c[1]), "+f"(c[2]), "+f"(c[3])
        : "r"(a0), "r"(a1), "r"(a2), "r"(a3), "r"(b0), "r"(b1));
}
#define LDSM4(r0, r1, r2, r3, addr) \
    asm volatile("ldmatrix.sync.aligned.m8n8.x4.shared.b16 {%0,%1,%2,%3}, [%4];" \
        : "=r"(r0), "=r"(r1), "=r"(r2), "=r"(r3) : "r"(addr))

// ---------------------------------------------------------------------------
// Kernel: e -> bf16
// ---------------------------------------------------------------------------
__global__ void conv_e_kernel(const float* __restrict__ e) {
    size_t i = ((size_t)blockIdx.x * 256 + threadIdx.x) * 8;
    float4 v0 = *reinterpret_cast<const float4*>(e + i);
    float4 v1 = *reinterpret_cast<const float4*>(e + i + 4);
    __nv_bfloat162 h[4];
    h[0] = __nv_bfloat162(__float2bfloat16(v0.x), __float2bfloat16(v0.y));
    h[1] = __nv_bfloat162(__float2bfloat16(v0.z), __float2bfloat16(v0.w));
    h[2] = __nv_bfloat162(__float2bfloat16(v1.x), __float2bfloat16(v1.y));
    h[3] = __nv_bfloat162(__float2bfloat16(v1.z), __float2bfloat16(v1.w));
    *reinterpret_cast<uint4*>(g_ebf + i) = *reinterpret_cast<uint4*>(h);
}

// ---------------------------------------------------------------------------
// Kernel A: a_p = sum_c fl(z^2), strictly sequential fp32, no FMA contraction.
// ---------------------------------------------------------------------------
__global__ void a_kernel(const float* __restrict__ z) {
    int p = blockIdx.x * 256 + threadIdx.x;
    int b = p >> 10, hw = p & 1023;
    const float* zp = z + (size_t)b * (DIM * 1024) + hw;
    float acc = 0.f;
    #pragma unroll 8
    for (int c = 0; c < DIM; c++) {
        float v = zp[(size_t)c * 1024];
        acc = __fadd_rn(acc, __fmul_rn(v, v));
    }
    g_a[p] = acc;
}

// No-op spacer kernels so ncu (-s 5 -c 1) lands on the GEMM launch.
__global__ void noop_kernel() {}

// ---------------------------------------------------------------------------
// Kernel B: BF16 tensor-core GEMM  y = z . E^T  + per-tile row max.
// mma.sync.m16n8k16 + ldmatrix. Block 512 thr = 16 warps (2M x 8N).
// M-tile 64, N-tile 256, K=256 in 32-half chunks, double buffered.
// ---------------------------------------------------------------------------
#define ZS_WSTRIDE 132          // z row stride in words (264 halves)
#define ES_WSTRIDE 20           // E row stride in words (40 halves)
#define ZS_WORDS (64 * ZS_WSTRIDE)
#define ES_WORDS (256 * ES_WSTRIDE)
#define GEMM_SMEM ((ZS_WORDS + 2 * ES_WORDS) * 4)

__global__ __launch_bounds__(512, 1)
void gemm_mma_kernel(const float* __restrict__ z) {
    extern __shared__ uint32_t smem[];
    uint32_t* zs_u = smem;                    // [64][ZS_WSTRIDE]
    uint32_t* es_u = smem + ZS_WORDS;         // [2][256][ES_WSTRIDE]
    __nv_bfloat16* zs_h = reinterpret_cast<__nv_bfloat16*>(zs_u);

    const int tid  = threadIdx.x;
    const int wid  = tid >> 5, lane = tid & 31;
    const int g    = lane >> 2, tig = lane & 3;
    const int wm   = wid & 1;          // warp row block (2 x 32 rows)
    const int wn   = wid >> 1;         // warp col block (8 x 32 cols)

    const int row0 = blockIdx.x * 64;
    const int b    = row0 >> 10;
    const int hw0  = row0 & 1023;
    const float* zbase = z + (size_t)b * (DIM * 1024) + hw0;

    // Load z tile as bf16: zs[r][c] = bf16(z[b, c, hw0 + r])
    for (int i = tid; i < 64 * 256; i += 512) {
        int c = i >> 6, r = i & 63;
        zs_h[r * 264 + c] = __float2bfloat16(zbase[(size_t)c * 1024 + r]);
    }
    __syncthreads();

    const uint4* eg = reinterpret_cast<const uint4*>(g_ebf);   // 32 uint4 per code row
    const int q  = tid & 3;            // uint4 slot within 32-half chunk
    const int n0 = tid >> 2;           // 0..127 code group (rows n0, n0+128)

    // ldmatrix base addresses (bytes)
    const uint32_t zs_base = smem_u32(zs_u);
    const uint32_t es_base = smem_u32(es_u);
    uint32_t aaddr[2];
    #pragma unroll
    for (int ms = 0; ms < 2; ms++)
        aaddr[ms] = zs_base +
            (((wm * 32 + ms * 16 + (lane & 15)) * ZS_WSTRIDE) + ((lane >> 4) & 1) * 4) * 4;
    uint32_t baddr[2];
    #pragma unroll
    for (int j = 0; j < 2; j++)
        baddr[j] = es_base +
            (((wn * 32 + j * 16 + (lane & 7) + ((lane & 16) >> 1)) * ES_WSTRIDE) +
             ((lane >> 3) & 1) * 4) * 4;

    for (int nb = 0; nb < NCODES; nb += 256) {
        float c[2][4][4];
        #pragma unroll
        for (int ms = 0; ms < 2; ms++)
            #pragma unroll
            for (int ns = 0; ns < 4; ns++)
                #pragma unroll
                for (int j = 0; j < 4; j++) c[ms][ns][j] = 0.f;

        // preload K-chunk 0 into buffer 0
        {
            uint4 pf[2];
            #pragma unroll
            for (int p = 0; p < 2; p++)
                pf[p] = eg[(size_t)(nb + n0 + 128 * p) * 32 + q];
            #pragma unroll
            for (int p = 0; p < 2; p++)
                *reinterpret_cast<uint4*>(&es_u[(n0 + 128 * p) * ES_WSTRIDE + 4 * q]) = pf[p];
        }
        __syncthreads();

        #pragma unroll
        for (int kc = 0; kc < 8; kc++) {
            uint4 pf[2];
            if (kc < 7) {
                #pragma unroll
                for (int p = 0; p < 2; p++)
                    pf[p] = eg[(size_t)(nb + n0 + 128 * p) * 32 + (kc + 1) * 4 + q];
            }

            const uint32_t bufoff = (uint32_t)((kc & 1) * ES_WORDS) * 4;
            const int kwb = kc * 16;

            #pragma unroll
            for (int ks = 0; ks < 2; ks++) {
                const uint32_t kofs_a = (uint32_t)(kwb + ks * 8) * 4;  // A: full-K tile
                const uint32_t kofs_b = (uint32_t)(ks * 8) * 4;        // B: within chunk
                uint32_t a[2][4], bfr[4][2];
                LDSM4(a[0][0], a[0][1], a[0][2], a[0][3], aaddr[0] + kofs_a);
                LDSM4(a[1][0], a[1][1], a[1][2], a[1][3], aaddr[1] + kofs_a);
                #pragma unroll
                for (int j = 0; j < 2; j++)
                    LDSM4(bfr[2 * j][0], bfr[2 * j][1], bfr[2 * j + 1][0], bfr[2 * j + 1][1],
                          baddr[j] + bufoff + kofs_b);
                #pragma unroll
                for (int ns = 0; ns < 4; ns++) {
                    mma_bf16(c[0][ns], a[0][0], a[0][1], a[0][2], a[0][3],
                             bfr[ns][0], bfr[ns][1]);
                    mma_bf16(c[1][ns], a[1][0], a[1][1], a[1][2], a[1][3],
                             bfr[ns][0], bfr[ns][1]);
                }
            }

            if (kc < 7) {
                uint32_t* wb = es_u + ((kc + 1) & 1) * ES_WORDS;
                #pragma unroll
                for (int p = 0; p < 2; p++)
                    *reinterpret_cast<uint4*>(&wb[(n0 + 128 * p) * ES_WSTRIDE + 4 * q]) = pf[p];
            }
            __syncthreads();
        }

        // Epilogue: y tile -> bf16 stores + per-thread tile max
        float rmax[4];
        #pragma unroll
        for (int i = 0; i < 4; i++) rmax[i] = -3.4e38f;

        #pragma unroll
        for (int ms = 0; ms < 2; ms++) {
            int r0 = row0 + wm * 32 + ms * 16 + g;
            #pragma unroll
            for (int ns = 0; ns < 4; ns++) {
                rmax[ms * 2]     = fmaxf(rmax[ms * 2],     fmaxf(c[ms][ns][0], c[ms][ns][1]));
                rmax[ms * 2 + 1] = fmaxf(rmax[ms * 2 + 1], fmaxf(c[ms][ns][2], c[ms][ns][3]));
                int col = nb + wn * 32 + ns * 8 + 2 * tig;
                __nv_bfloat162 lo(__float2bfloat16(c[ms][ns][0]), __float2bfloat16(c[ms][ns][1]));
                __nv_bfloat162 hi(__float2bfloat16(c[ms][ns][2]), __float2bfloat16(c[ms][ns][3]));
                *reinterpret_cast<__nv_bfloat162*>(&g_ybf[(size_t)r0 * NCODES + col]) = lo;
                *reinterpret_cast<__nv_bfloat162*>(&g_ybf[(size_t)(r0 + 8) * NCODES + col]) = hi;
            }
        }

        // Reduce tile max across the 32 threads sharing each row
        float* rm = reinterpret_cast<float*>(es_u);   // E buffers idle here
        #pragma unroll
        for (int ms = 0; ms < 2; ms++)
            #pragma unroll
            for (int half = 0; half < 2; half++) {
                int rl = wm * 32 + ms * 16 + g + half * 8;
                rm[rl * 32 + wn * 4 + tig] = rmax[ms * 2 + half];
            }
        __syncthreads();
        if (tid < 64) {
            float m = -3.4e38f;
            #pragma unroll
            for (int j = 0; j < 32; j++) m = fmaxf(m, rm[tid * 32 + j]);
            g_tmax[(size_t)(row0 + tid) * 64 + (nb >> 8)] = m;
        }
        __syncthreads();
    }
}

// ---------------------------------------------------------------------------
// Kernel C: tile-gated refine. rowmax from g_tmax; scan only tiles whose max
// clears rowmax - MARGIN; fp64 recompute; reference rounding; first-index ties.
// ---------------------------------------------------------------------------
#define MARGIN 1.2e-4f
#define MAXCAND 64

__global__ void refine_kernel(const float* __restrict__ z,
                              const float* __restrict__ e) {
    __shared__ float s_z[256];
    __shared__ float s_red[256];
    __shared__ float s_tmax[64];
    __shared__ int   s_cand[MAXCAND];
    __shared__ float s_d[MAXCAND];
    __shared__ int   s_cnt;

    const int p = blockIdx.x;
    const int b = p >> 10, hw = p & 1023;
    const int t = threadIdx.x;

    s_z[t] = z[(size_t)b * (DIM * 1024) + (size_t)t * 1024 + hw];
    if (t == 0) s_cnt = 0;

    float tm = -3.4e38f;
    if (t < 64) { tm = g_tmax[(size_t)p * 64 + t]; s_tmax[t] = tm; }
    s_red[t] = tm;
    __syncthreads();
    for (int s = 128; s; s >>= 1) {
        if (t < s) s_red[t] = fmaxf(s_red[t], s_red[t + s]);
        __syncthreads();
    }
    const float thr = s_red[0] - MARGIN;

    const __nv_bfloat16* yrow = g_ybf + (size_t)p * NCODES;
    for (int tt = 0; tt < 64; tt++) {
        if (s_tmax[tt] > thr) {
            float v = __bfloat162float(yrow[tt * 256 + t]);
            if (v > thr) {
                int slot = atomicAdd(&s_cnt, 1);
                if (slot < MAXCAND) s_cand[slot] = tt * 256 + t;
            }
        }
    }
    __syncthreads();

    const int cnt = min(s_cnt, MAXCAND);
    const float a = g_a[p];
    const int wid = t >> 5, lane = t & 31;

    for (int ci = wid; ci < cnt; ci += 8) {
        const float* er = e + (size_t)s_cand[ci] * DIM;
        double acc = 0.0;
        #pragma unroll
        for (int j = 0; j < 8; j++) {
            int cc = lane + 32 * j;
            acc += (double)s_z[cc] * (double)er[cc];
        }
        #pragma unroll
        for (int mlt = 16; mlt; mlt >>= 1)
            acc += __shfl_xor_sync(0xffffffffu, acc, mlt);
        if (lane == 0) {
            float y32 = (float)acc;
            s_d[ci] = __fsub_rn(a, __fmul_rn(2.0f, y32));
        }
    }
    __syncthreads();

    if (t == 0) {
        float bd = 3.4e38f; int bn = 0x7fffffff;
        for (int ci = 0; ci < cnt; ci++) {
            float d = s_d[ci]; int n = s_cand[ci];
            if (d < bd || (d == bd && n < bn)) { bd = d; bn = n; }
        }
        g_idx[p] = bn;
    }
}

// ---------------------------------------------------------------------------
// Kernel D: gather + straight-through rounding emulation + partial loss sums.
// ---------------------------------------------------------------------------
__global__ void gather_loss_kernel(const float* __restrict__ z,
                                   const float* __restrict__ e,
                                   float* __restrict__ out) {
    __shared__ float red[256];
    float acc = 0.f;
    for (int i = blockIdx.x * 256 + threadIdx.x; i < ZELEMS; i += 2048 * 256) {
        int bidx = i >> 18;
        int c    = (i >> 10) & 255;
        int hw   = i & 1023;
        int n    = g_idx[(bidx << 10) | hw];
        float v  = e[(size_t)n * DIM + c];
        float zb = z[i];
        float d  = __fsub_rn(v, zb);
        out[i]   = __fadd_rn(zb, d);
        acc += d * d;
    }
    red[threadIdx.x] = acc;
    __syncthreads();
    for (int s = 128; s; s >>= 1) {
        if (threadIdx.x < s) red[threadIdx.x] += red[threadIdx.x + s];
        __syncthreads();
    }
    if (threadIdx.x == 0) g_part[blockIdx.x] = red[0];
}

// ---------------------------------------------------------------------------
// Kernel E: final loss. loss = (BETA + 1) * mean = 2 * sum / ZELEMS
// ---------------------------------------------------------------------------
__global__ void loss_kernel(float* __restrict__ out, int out_size) {
    __shared__ float red[256];
    float acc = 0.f;
    for (int t = threadIdx.x; t < 2048; t += 256) acc += g_part[t];
    red[threadIdx.x] = acc;
    __syncthreads();
    for (int s = 128; s; s >>= 1) {
        if (threadIdx.x < s) red[threadIdx.x] += red[threadIdx.x + s];
        __syncthreads();
    }
    if (threadIdx.x == 0 && out_size > ZELEMS)
        out[ZELEMS] = 2.0f * red[0] / (float)ZELEMS;
}

// ---------------------------------------------------------------------------
extern "C" void kernel_launch(void* const* d_in, const int* in_sizes, int n_in,
                              void* d_out, int out_size) {
    const float* z = (const float*)d_in[0];   // (8,256,32,32) f32
    const float* e = (const float*)d_in[1];   // (16384,256)   f32
    float* out = (float*)d_out;

    cudaFuncSetAttribute(gemm_mma_kernel,
                         cudaFuncAttributeMaxDynamicSharedMemorySize, GEMM_SMEM);

    conv_e_kernel<<<2048, 256>>>(e);
    a_kernel<<<PTOT / 256, 256>>>(z);
    // spacers: make the GEMM the 6th launch so ncu -s 5 -c 1 profiles it
    noop_kernel<<<1, 32>>>();
    noop_kernel<<<1, 32>>>();
    noop_kernel<<<1, 32>>>();
    gemm_mma_kernel<<<PTOT / 64, 512, GEMM_SMEM>>>(z);
    refine_kernel<<<PTOT, 256>>>(z, e);
    gather_loss_kernel<<<2048, 256>>>(z, e, out);
    loss_kernel<<<1, 256>>>(out, out_size);
}

// round 15
// speedup vs baseline: 1.4417x; 1.0109x over previous
#include <cuda_runtime.h>
#include <cuda_bf16.h>
#include <cstdint>

// Problem constants
#define PTOT   8192        // B*H*W points
#define NCODES 16384
#define DIM    256
#define ZELEMS 2097152     // 8*256*32*32

// Scratch (static device globals; no allocations allowed)
__device__ float          g_a[PTOT];          // sequential fp32 ||z_row||^2
__device__ int            g_idx[PTOT];
__device__ float          g_part[2048];
__device__ float          g_tmax[(size_t)PTOT * 64];       // per-row per-256-tile max
__device__ __nv_bfloat16  g_ebf[(size_t)NCODES * DIM];     // codebook bf16
__device__ __nv_bfloat16  g_ybf[(size_t)PTOT * NCODES];    // 256 MB y matrix (bf16)

// ---------------------------------------------------------------------------
__device__ __forceinline__ uint32_t smem_u32(const void* p) {
    uint32_t a;
    asm("{ .reg .u64 t; cvta.to.shared.u64 t, %1; cvt.u32.u64 %0, t; }" : "=r"(a) : "l"(p));
    return a;
}
__device__ __forceinline__ void mma_bf16(float c[4],
                                         uint32_t a0, uint32_t a1, uint32_t a2, uint32_t a3,
                                         uint32_t b0, uint32_t b1) {
    asm volatile(
        "mma.sync.aligned.m16n8k16.row.col.f32.bf16.bf16.f32 "
        "{%0,%1,%2,%3}, {%4,%5,%6,%7}, {%8,%9}, {%0,%1,%2,%3};\n"
        : "+f"(c[0]), "+f"(c[1]), "+f"(c[2]), "+f"(c[3])
        : "r"(a0), "r"(a1), "r"(a2), "r"(a3), "r"(b0), "r"(b1));
}
#define LDSM4(r0, r1, r2, r3, addr) \
    asm volatile("ldmatrix.sync.aligned.m8n8.x4.shared.b16 {%0,%1,%2,%3}, [%4];" \
        : "=r"(r0), "=r"(r1), "=r"(r2), "=r"(r3) : "r"(addr))

// ---------------------------------------------------------------------------
// Kernel: e -> bf16
// ---------------------------------------------------------------------------
__global__ void conv_e_kernel(const float* __restrict__ e) {
    size_t i = ((size_t)blockIdx.x * 256 + threadIdx.x) * 8;
    float4 v0 = *reinterpret_cast<const float4*>(e + i);
    float4 v1 = *reinterpret_cast<const float4*>(e + i + 4);
    __nv_bfloat162 h[4];
    h[0] = __nv_bfloat162(__float2bfloat16(v0.x), __float2bfloat16(v0.y));
    h[1] = __nv_bfloat162(__float2bfloat16(v0.z), __float2bfloat16(v0.w));
    h[2] = __nv_bfloat162(__float2bfloat16(v1.x), __float2bfloat16(v1.y));
    h[3] = __nv_bfloat162(__float2bfloat16(v1.z), __float2bfloat16(v1.w));
    *reinterpret_cast<uint4*>(g_ebf + i) = *reinterpret_cast<uint4*>(h);
}

// ---------------------------------------------------------------------------
// Kernel A: a_p = sum_c fl(z^2), strictly sequential fp32, no FMA contraction.
// ---------------------------------------------------------------------------
__global__ void a_kernel(const float* __restrict__ z) {
    int p = blockIdx.x * 256 + threadIdx.x;
    int b = p >> 10, hw = p & 1023;
    const float* zp = z + (size_t)b * (DIM * 1024) + hw;
    float acc = 0.f;
    #pragma unroll 8
    for (int c = 0; c < DIM; c++) {
        float v = zp[(size_t)c * 1024];
        acc = __fadd_rn(acc, __fmul_rn(v, v));
    }
    g_a[p] = acc;
}

// ---------------------------------------------------------------------------
// Kernel B: BF16 tensor-core GEMM  y = z . E^T  + per-tile row max.
// mma.sync.m16n8k16 + ldmatrix. Block 256 thr = 8 warps (2M x 4N).
// M-tile 64, N-tile 256, K=256 in 32-half chunks, double buffered.
// (R12 version — at the legacy mma.sync roofline.)
// ---------------------------------------------------------------------------
#define ZS_WSTRIDE 132          // z row stride in words (264 halves)
#define ES_WSTRIDE 20           // E row stride in words (40 halves)
#define ZS_WORDS (64 * ZS_WSTRIDE)
#define ES_WORDS (256 * ES_WSTRIDE)
#define GEMM_SMEM ((ZS_WORDS + 2 * ES_WORDS) * 4)

__global__ __launch_bounds__(256, 1)
void gemm_mma_kernel(const float* __restrict__ z) {
    extern __shared__ uint32_t smem[];
    uint32_t* zs_u = smem;                    // [64][ZS_WSTRIDE]
    uint32_t* es_u = smem + ZS_WORDS;         // [2][256][ES_WSTRIDE]
    __nv_bfloat16* zs_h = reinterpret_cast<__nv_bfloat16*>(zs_u);

    const int tid  = threadIdx.x;
    const int wid  = tid >> 5, lane = tid & 31;
    const int g    = lane >> 2, tig = lane & 3;
    const int wm   = wid & 1;          // warp row block (2 x 32 rows)
    const int wn   = wid >> 1;         // warp col block (4 x 64 cols)

    const int row0 = blockIdx.x * 64;
    const int b    = row0 >> 10;
    const int hw0  = row0 & 1023;
    const float* zbase = z + (size_t)b * (DIM * 1024) + hw0;

    // Load z tile as bf16: zs[r][c] = bf16(z[b, c, hw0 + r])
    for (int i = tid; i < 64 * 256; i += 256) {
        int c = i >> 6, r = i & 63;
        zs_h[r * 264 + c] = __float2bfloat16(zbase[(size_t)c * 1024 + r]);
    }
    __syncthreads();

    const uint4* eg = reinterpret_cast<const uint4*>(g_ebf);   // 32 uint4 per code row
    const int q  = tid & 3;            // uint4 slot within 32-half chunk
    const int n0 = tid >> 2;           // 0..63 code group

    // ldmatrix base addresses (bytes)
    const uint32_t zs_base = smem_u32(zs_u);
    const uint32_t es_base = smem_u32(es_u);
    uint32_t aaddr[2];
    #pragma unroll
    for (int ms = 0; ms < 2; ms++)
        aaddr[ms] = zs_base +
            (((wm * 32 + ms * 16 + (lane & 15)) * ZS_WSTRIDE) + ((lane >> 4) & 1) * 4) * 4;
    uint32_t baddr[4];
    #pragma unroll
    for (int j = 0; j < 4; j++)
        baddr[j] = es_base +
            (((wn * 64 + j * 16 + (lane & 7) + ((lane & 16) >> 1)) * ES_WSTRIDE) +
             ((lane >> 3) & 1) * 4) * 4;

    for (int nb = 0; nb < NCODES; nb += 256) {
        float c[2][8][4];
        #pragma unroll
        for (int ms = 0; ms < 2; ms++)
            #pragma unroll
            for (int ns = 0; ns < 8; ns++)
                #pragma unroll
                for (int j = 0; j < 4; j++) c[ms][ns][j] = 0.f;

        // preload K-chunk 0 into buffer 0
        {
            uint4 pf[4];
            #pragma unroll
            for (int p = 0; p < 4; p++)
                pf[p] = eg[(size_t)(nb + n0 + 64 * p) * 32 + q];
            #pragma unroll
            for (int p = 0; p < 4; p++)
                *reinterpret_cast<uint4*>(&es_u[(n0 + 64 * p) * ES_WSTRIDE + 4 * q]) = pf[p];
        }
        __syncthreads();

        #pragma unroll
        for (int kc = 0; kc < 8; kc++) {
            uint4 pf[4];
            if (kc < 7) {
                #pragma unroll
                for (int p = 0; p < 4; p++)
                    pf[p] = eg[(size_t)(nb + n0 + 64 * p) * 32 + (kc + 1) * 4 + q];
            }

            const uint32_t bufoff = (uint32_t)((kc & 1) * ES_WORDS) * 4;
            const int kwb = kc * 16;

            #pragma unroll
            for (int ks = 0; ks < 2; ks++) {
                const uint32_t kofs_a = (uint32_t)(kwb + ks * 8) * 4;  // A: full-K tile
                const uint32_t kofs_b = (uint32_t)(ks * 8) * 4;        // B: within chunk
                uint32_t a[2][4], bfr[8][2];
                LDSM4(a[0][0], a[0][1], a[0][2], a[0][3], aaddr[0] + kofs_a);
                LDSM4(a[1][0], a[1][1], a[1][2], a[1][3], aaddr[1] + kofs_a);
                #pragma unroll
                for (int j = 0; j < 4; j++)
                    LDSM4(bfr[2 * j][0], bfr[2 * j][1], bfr[2 * j + 1][0], bfr[2 * j + 1][1],
                          baddr[j] + bufoff + kofs_b);
                #pragma unroll
                for (int ns = 0; ns < 8; ns++) {
                    mma_bf16(c[0][ns], a[0][0], a[0][1], a[0][2], a[0][3],
                             bfr[ns][0], bfr[ns][1]);
                    mma_bf16(c[1][ns], a[1][0], a[1][1], a[1][2], a[1][3],
                             bfr[ns][0], bfr[ns][1]);
                }
            }

            if (kc < 7) {
                uint32_t* wb = es_u + ((kc + 1) & 1) * ES_WORDS;
                #pragma unroll
                for (int p = 0; p < 4; p++)
                    *reinterpret_cast<uint4*>(&wb[(n0 + 64 * p) * ES_WSTRIDE + 4 * q]) = pf[p];
            }
            __syncthreads();
        }

        // Epilogue: y tile -> bf16 stores + per-thread tile max
        float rmax[4];
        #pragma unroll
        for (int i = 0; i < 4; i++) rmax[i] = -3.4e38f;

        #pragma unroll
        for (int ms = 0; ms < 2; ms++) {
            int r0 = row0 + wm * 32 + ms * 16 + g;
            #pragma unroll
            for (int ns = 0; ns < 8; ns++) {
                rmax[ms * 2]     = fmaxf(rmax[ms * 2],     fmaxf(c[ms][ns][0], c[ms][ns][1]));
                rmax[ms * 2 + 1] = fmaxf(rmax[ms * 2 + 1], fmaxf(c[ms][ns][2], c[ms][ns][3]));
                int col = nb + wn * 64 + ns * 8 + 2 * tig;
                __nv_bfloat162 lo(__float2bfloat16(c[ms][ns][0]), __float2bfloat16(c[ms][ns][1]));
                __nv_bfloat162 hi(__float2bfloat16(c[ms][ns][2]), __float2bfloat16(c[ms][ns][3]));
                *reinterpret_cast<__nv_bfloat162*>(&g_ybf[(size_t)r0 * NCODES + col]) = lo;
                *reinterpret_cast<__nv_bfloat162*>(&g_ybf[(size_t)(r0 + 8) * NCODES + col]) = hi;
            }
        }

        // Reduce tile max across the 16 threads per row; store g_tmax[row][tile]
        float* rm = reinterpret_cast<float*>(es_u);   // E buffers idle here
        #pragma unroll
        for (int ms = 0; ms < 2; ms++)
            #pragma unroll
            for (int half = 0; half < 2; half++) {
                int rl = wm * 32 + ms * 16 + g + half * 8;
                rm[rl * 16 + wn * 4 + tig] = rmax[ms * 2 + half];
            }
        __syncthreads();
        if (tid < 64) {
            float m = -3.4e38f;
            #pragma unroll
            for (int j = 0; j < 16; j++) m = fmaxf(m, rm[tid * 16 + j]);
            g_tmax[(size_t)(row0 + tid) * 64 + (nb >> 8)] = m;
        }
        __syncthreads();
    }
}

// ---------------------------------------------------------------------------
// Kernel C: tile-gated refine with cnt==1 fast path.
// If exactly one candidate clears rowmax - MARGIN, it IS the argmin (the
// margin dominates the total emulation error band) -> write directly.
// Else: fp64 recompute, reference rounding d = fl(a - fl(2*fl32(y))),
// first-index ties. s_z loaded lazily only on the slow path.
// ---------------------------------------------------------------------------
#define MARGIN 1.2e-4f
#define MAXCAND 64

__global__ void refine_kernel(const float* __restrict__ z,
                              const float* __restrict__ e) {
    __shared__ float s_z[256];
    __shared__ float s_red[256];
    __shared__ float s_tmax[64];
    __shared__ int   s_cand[MAXCAND];
    __shared__ float s_d[MAXCAND];
    __shared__ int   s_cnt;

    const int p = blockIdx.x;
    const int b = p >> 10, hw = p & 1023;
    const int t = threadIdx.x;

    if (t == 0) s_cnt = 0;

    float tm = -3.4e38f;
    if (t < 64) { tm = g_tmax[(size_t)p * 64 + t]; s_tmax[t] = tm; }
    s_red[t] = tm;
    __syncthreads();
    for (int s = 128; s; s >>= 1) {
        if (t < s) s_red[t] = fmaxf(s_red[t], s_red[t + s]);
        __syncthreads();
    }
    const float thr = s_red[0] - MARGIN;

    const __nv_bfloat16* yrow = g_ybf + (size_t)p * NCODES;
    for (int tt = 0; tt < 64; tt++) {
        if (s_tmax[tt] > thr) {
            float v = __bfloat162float(yrow[tt * 256 + t]);
            if (v > thr) {
                int slot = atomicAdd(&s_cnt, 1);
                if (slot < MAXCAND) s_cand[slot] = tt * 256 + t;
            }
        }
    }
    __syncthreads();

    const int cnt = min(s_cnt, MAXCAND);
    if (cnt == 1) {                       // fast path: sole candidate = argmin
        if (t == 0) g_idx[p] = s_cand[0];
        return;
    }

    // slow path: load z row, fp64 recompute candidates
    s_z[t] = z[(size_t)b * (DIM * 1024) + (size_t)t * 1024 + hw];
    __syncthreads();

    const float a = g_a[p];
    const int wid = t >> 5, lane = t & 31;

    for (int ci = wid; ci < cnt; ci += 8) {
        const float* er = e + (size_t)s_cand[ci] * DIM;
        double acc = 0.0;
        #pragma unroll
        for (int j = 0; j < 8; j++) {
            int cc = lane + 32 * j;
            acc += (double)s_z[cc] * (double)er[cc];
        }
        #pragma unroll
        for (int mlt = 16; mlt; mlt >>= 1)
            acc += __shfl_xor_sync(0xffffffffu, acc, mlt);
        if (lane == 0) {
            float y32 = (float)acc;
            s_d[ci] = __fsub_rn(a, __fmul_rn(2.0f, y32));
        }
    }
    __syncthreads();

    if (t == 0) {
        float bd = 3.4e38f; int bn = 0x7fffffff;
        for (int ci = 0; ci < cnt; ci++) {
            float d = s_d[ci]; int n = s_cand[ci];
            if (d < bd || (d == bd && n < bn)) { bd = d; bn = n; }
        }
        g_idx[p] = bn;
    }
}

// ---------------------------------------------------------------------------
// Kernel D: gather + straight-through rounding emulation + partial loss sums.
// ---------------------------------------------------------------------------
__global__ void gather_loss_kernel(const float* __restrict__ z,
                                   const float* __restrict__ e,
                                   float* __restrict__ out) {
    __shared__ float red[256];
    float acc = 0.f;
    for (int i = blockIdx.x * 256 + threadIdx.x; i < ZELEMS; i += 2048 * 256) {
        int bidx = i >> 18;
        int c    = (i >> 10) & 255;
        int hw   = i & 1023;
        int n    = g_idx[(bidx << 10) | hw];
        float v  = e[(size_t)n * DIM + c];
        float zb = z[i];
        float d  = __fsub_rn(v, zb);
        out[i]   = __fadd_rn(zb, d);
        acc += d * d;
    }
    red[threadIdx.x] = acc;
    __syncthreads();
    for (int s = 128; s; s >>= 1) {
        if (threadIdx.x < s) red[threadIdx.x] += red[threadIdx.x + s];
        __syncthreads();
    }
    if (threadIdx.x == 0) g_part[blockIdx.x] = red[0];
}

// ---------------------------------------------------------------------------
// Kernel E: final loss. loss = (BETA + 1) * mean = 2 * sum / ZELEMS
// ---------------------------------------------------------------------------
__global__ void loss_kernel(float* __restrict__ out, int out_size) {
    __shared__ float red[256];
    float acc = 0.f;
    for (int t = threadIdx.x; t < 2048; t += 256) acc += g_part[t];
    red[threadIdx.x] = acc;
    __syncthreads();
    for (int s = 128; s; s >>= 1) {
        if (threadIdx.x < s) red[threadIdx.x] += red[threadIdx.x + s];
        __syncthreads();
    }
    if (threadIdx.x == 0 && out_size > ZELEMS)
        out[ZELEMS] = 2.0f * red[0] / (float)ZELEMS;
}

// ---------------------------------------------------------------------------
extern "C" void kernel_launch(void* const* d_in, const int* in_sizes, int n_in,
                              void* d_out, int out_size) {
    const float* z = (const float*)d_in[0];   // (8,256,32,32) f32
    const float* e = (const float*)d_in[1];   // (16384,256)   f32
    float* out = (float*)d_out;

    cudaFuncSetAttribute(gemm_mma_kernel,
                         cudaFuncAttributeMaxDynamicSharedMemorySize, GEMM_SMEM);

    conv_e_kernel<<<2048, 256>>>(e);
    a_kernel<<<PTOT / 256, 256>>>(z);
    gemm_mma_kernel<<<PTOT / 64, 256, GEMM_SMEM>>>(z);
    refine_kernel<<<PTOT, 256>>>(z, e);
    gather_loss_kernel<<<2048, 256>>>(z, e, out);
    loss_kernel<<<1, 256>>>(out, out_size);
}

// round 16
// speedup vs baseline: 1.4964x; 1.0380x over previous
#include <cuda_runtime.h>
#include <cuda_bf16.h>
#include <cstdint>

// Problem constants
#define PTOT   8192        // B*H*W points
#define NCODES 16384
#define DIM    256
#define ZELEMS 2097152     // 8*256*32*32

// Scratch (static device globals; no allocations allowed)
__device__ float          g_a[PTOT];          // sequential fp32 ||z_row||^2
__device__ int            g_idx[PTOT];
__device__ float          g_part[2048];
__device__ float          g_rowmax[PTOT];     // per-row max of y (fp32, from GEMM)
__device__ float          g_tmax[(size_t)PTOT * 64];       // per-row per-256-tile max
__device__ __nv_bfloat16  g_ebf[(size_t)NCODES * DIM];     // codebook bf16
__device__ __nv_bfloat16  g_ybf[(size_t)PTOT * NCODES];    // 256 MB y matrix (bf16)

// ---------------------------------------------------------------------------
__device__ __forceinline__ uint32_t smem_u32(const void* p) {
    uint32_t a;
    asm("{ .reg .u64 t; cvta.to.shared.u64 t, %1; cvt.u32.u64 %0, t; }" : "=r"(a) : "l"(p));
    return a;
}
__device__ __forceinline__ void mma_bf16(float c[4],
                                         uint32_t a0, uint32_t a1, uint32_t a2, uint32_t a3,
                                         uint32_t b0, uint32_t b1) {
    asm volatile(
        "mma.sync.aligned.m16n8k16.row.col.f32.bf16.bf16.f32 "
        "{%0,%1,%2,%3}, {%4,%5,%6,%7}, {%8,%9}, {%0,%1,%2,%3};\n"
        : "+f"(c[0]), "+f"(c[1]), "+f"(c[2]), "+f"(c[3])
        : "r"(a0), "r"(a1), "r"(a2), "r"(a3), "r"(b0), "r"(b1));
}
#define LDSM4(r0, r1, r2, r3, addr) \
    asm volatile("ldmatrix.sync.aligned.m8n8.x4.shared.b16 {%0,%1,%2,%3}, [%4];" \
        : "=r"(r0), "=r"(r1), "=r"(r2), "=r"(r3) : "r"(addr))

// ---------------------------------------------------------------------------
// Kernel: e -> bf16
// ---------------------------------------------------------------------------
__global__ void conv_e_kernel(const float* __restrict__ e) {
    size_t i = ((size_t)blockIdx.x * 256 + threadIdx.x) * 8;
    float4 v0 = *reinterpret_cast<const float4*>(e + i);
    float4 v1 = *reinterpret_cast<const float4*>(e + i + 4);
    __nv_bfloat162 h[4];
    h[0] = __nv_bfloat162(__float2bfloat16(v0.x), __float2bfloat16(v0.y));
    h[1] = __nv_bfloat162(__float2bfloat16(v0.z), __float2bfloat16(v0.w));
    h[2] = __nv_bfloat162(__float2bfloat16(v1.x), __float2bfloat16(v1.y));
    h[3] = __nv_bfloat162(__float2bfloat16(v1.z), __float2bfloat16(v1.w));
    *reinterpret_cast<uint4*>(g_ebf + i) = *reinterpret_cast<uint4*>(h);
}

// ---------------------------------------------------------------------------
// Kernel A: a_p = sum_c fl(z^2), strictly sequential fp32, no FMA contraction.
// ---------------------------------------------------------------------------
__global__ void a_kernel(const float* __restrict__ z) {
    int p = blockIdx.x * 256 + threadIdx.x;
    int b = p >> 10, hw = p & 1023;
    const float* zp = z + (size_t)b * (DIM * 1024) + hw;
    float acc = 0.f;
    #pragma unroll 8
    for (int c = 0; c < DIM; c++) {
        float v = zp[(size_t)c * 1024];
        acc = __fadd_rn(acc, __fmul_rn(v, v));
    }
    g_a[p] = acc;
}

// ---------------------------------------------------------------------------
// Kernel B: BF16 tensor-core GEMM  y = z . E^T  + per-tile max + row max.
// mma.sync.m16n8k16 + ldmatrix. Block 256 thr = 8 warps (2M x 4N).
// M-tile 64, N-tile 256, K=256 in 32-half chunks, double buffered.
// ---------------------------------------------------------------------------
#define ZS_WSTRIDE 132          // z row stride in words (264 halves)
#define ES_WSTRIDE 20           // E row stride in words (40 halves)
#define ZS_WORDS (64 * ZS_WSTRIDE)
#define ES_WORDS (256 * ES_WSTRIDE)
#define GEMM_SMEM ((ZS_WORDS + 2 * ES_WORDS) * 4)

__global__ __launch_bounds__(256, 1)
void gemm_mma_kernel(const float* __restrict__ z) {
    extern __shared__ uint32_t smem[];
    uint32_t* zs_u = smem;                    // [64][ZS_WSTRIDE]
    uint32_t* es_u = smem + ZS_WORDS;         // [2][256][ES_WSTRIDE]
    __nv_bfloat16* zs_h = reinterpret_cast<__nv_bfloat16*>(zs_u);

    const int tid  = threadIdx.x;
    const int wid  = tid >> 5, lane = tid & 31;
    const int g    = lane >> 2, tig = lane & 3;
    const int wm   = wid & 1;          // warp row block (2 x 32 rows)
    const int wn   = wid >> 1;         // warp col block (4 x 64 cols)

    const int row0 = blockIdx.x * 64;
    const int b    = row0 >> 10;
    const int hw0  = row0 & 1023;
    const float* zbase = z + (size_t)b * (DIM * 1024) + hw0;

    // Load z tile as bf16: zs[r][c] = bf16(z[b, c, hw0 + r])
    for (int i = tid; i < 64 * 256; i += 256) {
        int c = i >> 6, r = i & 63;
        zs_h[r * 264 + c] = __float2bfloat16(zbase[(size_t)c * 1024 + r]);
    }
    __syncthreads();

    const uint4* eg = reinterpret_cast<const uint4*>(g_ebf);   // 32 uint4 per code row
    const int q  = tid & 3;            // uint4 slot within 32-half chunk
    const int n0 = tid >> 2;           // 0..63 code group

    // ldmatrix base addresses (bytes)
    const uint32_t zs_base = smem_u32(zs_u);
    const uint32_t es_base = smem_u32(es_u);
    uint32_t aaddr[2];
    #pragma unroll
    for (int ms = 0; ms < 2; ms++)
        aaddr[ms] = zs_base +
            (((wm * 32 + ms * 16 + (lane & 15)) * ZS_WSTRIDE) + ((lane >> 4) & 1) * 4) * 4;
    uint32_t baddr[4];
    #pragma unroll
    for (int j = 0; j < 4; j++)
        baddr[j] = es_base +
            (((wn * 64 + j * 16 + (lane & 7) + ((lane & 16) >> 1)) * ES_WSTRIDE) +
             ((lane >> 3) & 1) * 4) * 4;

    float rowm = -3.4e38f;             // running row max (used by tid < 64)

    for (int nb = 0; nb < NCODES; nb += 256) {
        float c[2][8][4];
        #pragma unroll
        for (int ms = 0; ms < 2; ms++)
            #pragma unroll
            for (int ns = 0; ns < 8; ns++)
                #pragma unroll
                for (int j = 0; j < 4; j++) c[ms][ns][j] = 0.f;

        // preload K-chunk 0 into buffer 0
        {
            uint4 pf[4];
            #pragma unroll
            for (int p = 0; p < 4; p++)
                pf[p] = eg[(size_t)(nb + n0 + 64 * p) * 32 + q];
            #pragma unroll
            for (int p = 0; p < 4; p++)
                *reinterpret_cast<uint4*>(&es_u[(n0 + 64 * p) * ES_WSTRIDE + 4 * q]) = pf[p];
        }
        __syncthreads();

        #pragma unroll
        for (int kc = 0; kc < 8; kc++) {
            uint4 pf[4];
            if (kc < 7) {
                #pragma unroll
                for (int p = 0; p < 4; p++)
                    pf[p] = eg[(size_t)(nb + n0 + 64 * p) * 32 + (kc + 1) * 4 + q];
            }

            const uint32_t bufoff = (uint32_t)((kc & 1) * ES_WORDS) * 4;
            const int kwb = kc * 16;

            #pragma unroll
            for (int ks = 0; ks < 2; ks++) {
                const uint32_t kofs_a = (uint32_t)(kwb + ks * 8) * 4;  // A: full-K tile
                const uint32_t kofs_b = (uint32_t)(ks * 8) * 4;        // B: within chunk
                uint32_t a[2][4], bfr[8][2];
                LDSM4(a[0][0], a[0][1], a[0][2], a[0][3], aaddr[0] + kofs_a);
                LDSM4(a[1][0], a[1][1], a[1][2], a[1][3], aaddr[1] + kofs_a);
                #pragma unroll
                for (int j = 0; j < 4; j++)
                    LDSM4(bfr[2 * j][0], bfr[2 * j][1], bfr[2 * j + 1][0], bfr[2 * j + 1][1],
                          baddr[j] + bufoff + kofs_b);
                #pragma unroll
                for (int ns = 0; ns < 8; ns++) {
                    mma_bf16(c[0][ns], a[0][0], a[0][1], a[0][2], a[0][3],
                             bfr[ns][0], bfr[ns][1]);
                    mma_bf16(c[1][ns], a[1][0], a[1][1], a[1][2], a[1][3],
                             bfr[ns][0], bfr[ns][1]);
                }
            }

            if (kc < 7) {
                uint32_t* wb = es_u + ((kc + 1) & 1) * ES_WORDS;
                #pragma unroll
                for (int p = 0; p < 4; p++)
                    *reinterpret_cast<uint4*>(&wb[(n0 + 64 * p) * ES_WSTRIDE + 4 * q]) = pf[p];
            }
            __syncthreads();
        }

        // Epilogue: y tile -> bf16 stores + per-thread tile max
        float rmax[4];
        #pragma unroll
        for (int i = 0; i < 4; i++) rmax[i] = -3.4e38f;

        #pragma unroll
        for (int ms = 0; ms < 2; ms++) {
            int r0 = row0 + wm * 32 + ms * 16 + g;
            #pragma unroll
            for (int ns = 0; ns < 8; ns++) {
                rmax[ms * 2]     = fmaxf(rmax[ms * 2],     fmaxf(c[ms][ns][0], c[ms][ns][1]));
                rmax[ms * 2 + 1] = fmaxf(rmax[ms * 2 + 1], fmaxf(c[ms][ns][2], c[ms][ns][3]));
                int col = nb + wn * 64 + ns * 8 + 2 * tig;
                __nv_bfloat162 lo(__float2bfloat16(c[ms][ns][0]), __float2bfloat16(c[ms][ns][1]));
                __nv_bfloat162 hi(__float2bfloat16(c[ms][ns][2]), __float2bfloat16(c[ms][ns][3]));
                *reinterpret_cast<__nv_bfloat162*>(&g_ybf[(size_t)r0 * NCODES + col]) = lo;
                *reinterpret_cast<__nv_bfloat162*>(&g_ybf[(size_t)(r0 + 8) * NCODES + col]) = hi;
            }
        }

        // Reduce tile max across the 16 threads per row; store g_tmax[row][tile]
        float* rm = reinterpret_cast<float*>(es_u);   // E buffers idle here
        #pragma unroll
        for (int ms = 0; ms < 2; ms++)
            #pragma unroll
            for (int half = 0; half < 2; half++) {
                int rl = wm * 32 + ms * 16 + g + half * 8;
                rm[rl * 16 + wn * 4 + tig] = rmax[ms * 2 + half];
            }
        __syncthreads();
        if (tid < 64) {
            float m = -3.4e38f;
            #pragma unroll
            for (int j = 0; j < 16; j++) m = fmaxf(m, rm[tid * 16 + j]);
            g_tmax[(size_t)(row0 + tid) * 64 + (nb >> 8)] = m;
            rowm = fmaxf(rowm, m);
        }
        __syncthreads();
    }

    if (tid < 64) g_rowmax[row0 + tid] = rowm;
}

// ---------------------------------------------------------------------------
// Kernel C: bitmask-gated refine. rowmax precomputed by GEMM; warps 0-1
// ballot live tiles into a 64-bit mask; scan only set bits. cnt==1 fast
// path; else fp64 recompute with reference rounding, first-index ties.
// ---------------------------------------------------------------------------
#define MARGIN 1.2e-4f
#define MAXCAND 64

__global__ void refine_kernel(const float* __restrict__ z,
                              const float* __restrict__ e) {
    __shared__ float    s_z[256];
    __shared__ int      s_cand[MAXCAND];
    __shared__ float    s_d[MAXCAND];
    __shared__ int      s_cnt;
    __shared__ uint32_t s_mask[2];

    const int p = blockIdx.x;
    const int b = p >> 10, hw = p & 1023;
    const int t = threadIdx.x;

    if (t == 0) s_cnt = 0;
    const float thr = g_rowmax[p] - MARGIN;

    if (t < 64) {
        float tm = g_tmax[(size_t)p * 64 + t];
        uint32_t m = __ballot_sync(0xffffffffu, tm > thr);
        if ((t & 31) == 0) s_mask[t >> 5] = m;
    }
    __syncthreads();

    uint64_t mask = (uint64_t)s_mask[0] | ((uint64_t)s_mask[1] << 32);
    const __nv_bfloat16* yrow = g_ybf + (size_t)p * NCODES;
    while (mask) {
        int tt = __ffsll((long long)mask) - 1;
        mask &= mask - 1;
        float v = __bfloat162float(yrow[tt * 256 + t]);
        if (v > thr) {
            int slot = atomicAdd(&s_cnt, 1);
            if (slot < MAXCAND) s_cand[slot] = tt * 256 + t;
        }
    }
    __syncthreads();

    const int cnt = min(s_cnt, MAXCAND);
    if (cnt == 1) {                       // fast path: sole candidate = argmin
        if (t == 0) g_idx[p] = s_cand[0];
        return;
    }

    // slow path: load z row, fp64 recompute candidates
    s_z[t] = z[(size_t)b * (DIM * 1024) + (size_t)t * 1024 + hw];
    __syncthreads();

    const float a = g_a[p];
    const int wid = t >> 5, lane = t & 31;

    for (int ci = wid; ci < cnt; ci += 8) {
        const float* er = e + (size_t)s_cand[ci] * DIM;
        double acc = 0.0;
        #pragma unroll
        for (int j = 0; j < 8; j++) {
            int cc = lane + 32 * j;
            acc += (double)s_z[cc] * (double)er[cc];
        }
        #pragma unroll
        for (int mlt = 16; mlt; mlt >>= 1)
            acc += __shfl_xor_sync(0xffffffffu, acc, mlt);
        if (lane == 0) {
            float y32 = (float)acc;
            s_d[ci] = __fsub_rn(a, __fmul_rn(2.0f, y32));
        }
    }
    __syncthreads();

    if (t == 0) {
        float bd = 3.4e38f; int bn = 0x7fffffff;
        for (int ci = 0; ci < cnt; ci++) {
            float d = s_d[ci]; int n = s_cand[ci];
            if (d < bd || (d == bd && n < bn)) { bd = d; bn = n; }
        }
        g_idx[p] = bn;
    }
}

// ---------------------------------------------------------------------------
// Kernel D: gather + straight-through rounding emulation + partial loss sums.
// ---------------------------------------------------------------------------
__global__ void gather_loss_kernel(const float* __restrict__ z,
                                   const float* __restrict__ e,
                                   float* __restrict__ out) {
    __shared__ float red[256];
    float acc = 0.f;
    for (int i = blockIdx.x * 256 + threadIdx.x; i < ZELEMS; i += 2048 * 256) {
        int bidx = i >> 18;
        int c    = (i >> 10) & 255;
        int hw   = i & 1023;
        int n    = g_idx[(bidx << 10) | hw];
        float v  = e[(size_t)n * DIM + c];
        float zb = z[i];
        float d  = __fsub_rn(v, zb);
        out[i]   = __fadd_rn(zb, d);
        acc += d * d;
    }
    red[threadIdx.x] = acc;
    __syncthreads();
    for (int s = 128; s; s >>= 1) {
        if (threadIdx.x < s) red[threadIdx.x] += red[threadIdx.x + s];
        __syncthreads();
    }
    if (threadIdx.x == 0) g_part[blockIdx.x] = red[0];
}

// ---------------------------------------------------------------------------
// Kernel E: final loss. loss = (BETA + 1) * mean = 2 * sum / ZELEMS
// ---------------------------------------------------------------------------
__global__ void loss_kernel(float* __restrict__ out, int out_size) {
    __shared__ float red[256];
    float acc = 0.f;
    for (int t = threadIdx.x; t < 2048; t += 256) acc += g_part[t];
    red[threadIdx.x] = acc;
    __syncthreads();
    for (int s = 128; s; s >>= 1) {
        if (threadIdx.x < s) red[threadIdx.x] += red[threadIdx.x + s];
        __syncthreads();
    }
    if (threadIdx.x == 0 && out_size > ZELEMS)
        out[ZELEMS] = 2.0f * red[0] / (float)ZELEMS;
}

// ---------------------------------------------------------------------------
extern "C" void kernel_launch(void* const* d_in, const int* in_sizes, int n_in,
                              void* d_out, int out_size) {
    const float* z = (const float*)d_in[0];   // (8,256,32,32) f32
    const float* e = (const float*)d_in[1];   // (16384,256)   f32
    float* out = (float*)d_out;

    cudaFuncSetAttribute(gemm_mma_kernel,
                         cudaFuncAttributeMaxDynamicSharedMemorySize, GEMM_SMEM);

    conv_e_kernel<<<2048, 256>>>(e);
    a_kernel<<<PTOT / 256, 256>>>(z);
    gemm_mma_kernel<<<PTOT / 64, 256, GEMM_SMEM>>>(z);
    refine_kernel<<<PTOT, 256>>>(z, e);
    gather_loss_kernel<<<2048, 256>>>(z, e, out);
    loss_kernel<<<1, 256>>>(out, out_size);
}

// round 17
// speedup vs baseline: 1.5006x; 1.0028x over previous
#include <cuda_runtime.h>
#include <cuda_bf16.h>
#include <cstdint>

// Problem constants
#define PTOT   8192        // B*H*W points
#define NCODES 16384
#define DIM    256
#define ZELEMS 2097152     // 8*256*32*32

// Scratch (static device globals; no allocations allowed)
__device__ int            g_idx[PTOT];
__device__ float          g_part[2048];
__device__ float          g_rowmax[PTOT];     // per-row max of y (fp32, from GEMM)
__device__ float          g_tmax[(size_t)PTOT * 64];       // per-row per-256-tile max
__device__ __nv_bfloat16  g_ebf[(size_t)NCODES * DIM];     // codebook bf16
__device__ __nv_bfloat16  g_ybf[(size_t)PTOT * NCODES];    // 256 MB y matrix (bf16)

// ---------------------------------------------------------------------------
__device__ __forceinline__ uint32_t smem_u32(const void* p) {
    uint32_t a;
    asm("{ .reg .u64 t; cvta.to.shared.u64 t, %1; cvt.u32.u64 %0, t; }" : "=r"(a) : "l"(p));
    return a;
}
__device__ __forceinline__ void mma_bf16(float c[4],
                                         uint32_t a0, uint32_t a1, uint32_t a2, uint32_t a3,
                                         uint32_t b0, uint32_t b1) {
    asm volatile(
        "mma.sync.aligned.m16n8k16.row.col.f32.bf16.bf16.f32 "
        "{%0,%1,%2,%3}, {%4,%5,%6,%7}, {%8,%9}, {%0,%1,%2,%3};\n"
        : "+f"(c[0]), "+f"(c[1]), "+f"(c[2]), "+f"(c[3])
        : "r"(a0), "r"(a1), "r"(a2), "r"(a3), "r"(b0), "r"(b1));
}
#define LDSM4(r0, r1, r2, r3, addr) \
    asm volatile("ldmatrix.sync.aligned.m8n8.x4.shared.b16 {%0,%1,%2,%3}, [%4];" \
        : "=r"(r0), "=r"(r1), "=r"(r2), "=r"(r3) : "r"(addr))

// ---------------------------------------------------------------------------
// Kernel: e -> bf16
// ---------------------------------------------------------------------------
__global__ void conv_e_kernel(const float* __restrict__ e) {
    size_t i = ((size_t)blockIdx.x * 256 + threadIdx.x) * 8;
    float4 v0 = *reinterpret_cast<const float4*>(e + i);
    float4 v1 = *reinterpret_cast<const float4*>(e + i + 4);
    __nv_bfloat162 h[4];
    h[0] = __nv_bfloat162(__float2bfloat16(v0.x), __float2bfloat16(v0.y));
    h[1] = __nv_bfloat162(__float2bfloat16(v0.z), __float2bfloat16(v0.w));
    h[2] = __nv_bfloat162(__float2bfloat16(v1.x), __float2bfloat16(v1.y));
    h[3] = __nv_bfloat162(__float2bfloat16(v1.z), __float2bfloat16(v1.w));
    *reinterpret_cast<uint4*>(g_ebf + i) = *reinterpret_cast<uint4*>(h);
}

// ---------------------------------------------------------------------------
// Kernel B: BF16 tensor-core GEMM  y = z . E^T  + per-tile max + row max.
// mma.sync.m16n8k16 + ldmatrix. Block 256 thr = 8 warps (2M x 4N).
// M-tile 64, N-tile 256, K=256 in 32-half chunks, double buffered.
// ---------------------------------------------------------------------------
#define ZS_WSTRIDE 132          // z row stride in words (264 halves)
#define ES_WSTRIDE 20           // E row stride in words (40 halves)
#define ZS_WORDS (64 * ZS_WSTRIDE)
#define ES_WORDS (256 * ES_WSTRIDE)
#define GEMM_SMEM ((ZS_WORDS + 2 * ES_WORDS) * 4)

__global__ __launch_bounds__(256, 1)
void gemm_mma_kernel(const float* __restrict__ z) {
    extern __shared__ uint32_t smem[];
    uint32_t* zs_u = smem;                    // [64][ZS_WSTRIDE]
    uint32_t* es_u = smem + ZS_WORDS;         // [2][256][ES_WSTRIDE]
    __nv_bfloat16* zs_h = reinterpret_cast<__nv_bfloat16*>(zs_u);

    const int tid  = threadIdx.x;
    const int wid  = tid >> 5, lane = tid & 31;
    const int g    = lane >> 2, tig = lane & 3;
    const int wm   = wid & 1;          // warp row block (2 x 32 rows)
    const int wn   = wid >> 1;         // warp col block (4 x 64 cols)

    const int row0 = blockIdx.x * 64;
    const int b    = row0 >> 10;
    const int hw0  = row0 & 1023;
    const float* zbase = z + (size_t)b * (DIM * 1024) + hw0;

    // Load z tile as bf16: zs[r][c] = bf16(z[b, c, hw0 + r])
    for (int i = tid; i < 64 * 256; i += 256) {
        int c = i >> 6, r = i & 63;
        zs_h[r * 264 + c] = __float2bfloat16(zbase[(size_t)c * 1024 + r]);
    }
    __syncthreads();

    const uint4* eg = reinterpret_cast<const uint4*>(g_ebf);   // 32 uint4 per code row
    const int q  = tid & 3;            // uint4 slot within 32-half chunk
    const int n0 = tid >> 2;           // 0..63 code group

    // ldmatrix base addresses (bytes)
    const uint32_t zs_base = smem_u32(zs_u);
    const uint32_t es_base = smem_u32(es_u);
    uint32_t aaddr[2];
    #pragma unroll
    for (int ms = 0; ms < 2; ms++)
        aaddr[ms] = zs_base +
            (((wm * 32 + ms * 16 + (lane & 15)) * ZS_WSTRIDE) + ((lane >> 4) & 1) * 4) * 4;
    uint32_t baddr[4];
    #pragma unroll
    for (int j = 0; j < 4; j++)
        baddr[j] = es_base +
            (((wn * 64 + j * 16 + (lane & 7) + ((lane & 16) >> 1)) * ES_WSTRIDE) +
             ((lane >> 3) & 1) * 4) * 4;

    float rowm = -3.4e38f;             // running row max (used by tid < 64)

    for (int nb = 0; nb < NCODES; nb += 256) {
        float c[2][8][4];
        #pragma unroll
        for (int ms = 0; ms < 2; ms++)
            #pragma unroll
            for (int ns = 0; ns < 8; ns++)
                #pragma unroll
                for (int j = 0; j < 4; j++) c[ms][ns][j] = 0.f;

        // preload K-chunk 0 into buffer 0
        {
            uint4 pf[4];
            #pragma unroll
            for (int p = 0; p < 4; p++)
                pf[p] = eg[(size_t)(nb + n0 + 64 * p) * 32 + q];
            #pragma unroll
            for (int p = 0; p < 4; p++)
                *reinterpret_cast<uint4*>(&es_u[(n0 + 64 * p) * ES_WSTRIDE + 4 * q]) = pf[p];
        }
        __syncthreads();

        #pragma unroll
        for (int kc = 0; kc < 8; kc++) {
            uint4 pf[4];
            if (kc < 7) {
                #pragma unroll
                for (int p = 0; p < 4; p++)
                    pf[p] = eg[(size_t)(nb + n0 + 64 * p) * 32 + (kc + 1) * 4 + q];
            }

            const uint32_t bufoff = (uint32_t)((kc & 1) * ES_WORDS) * 4;
            const int kwb = kc * 16;

            #pragma unroll
            for (int ks = 0; ks < 2; ks++) {
                const uint32_t kofs_a = (uint32_t)(kwb + ks * 8) * 4;  // A: full-K tile
                const uint32_t kofs_b = (uint32_t)(ks * 8) * 4;        // B: within chunk
                uint32_t a[2][4], bfr[8][2];
                LDSM4(a[0][0], a[0][1], a[0][2], a[0][3], aaddr[0] + kofs_a);
                LDSM4(a[1][0], a[1][1], a[1][2], a[1][3], aaddr[1] + kofs_a);
                #pragma unroll
                for (int j = 0; j < 4; j++)
                    LDSM4(bfr[2 * j][0], bfr[2 * j][1], bfr[2 * j + 1][0], bfr[2 * j + 1][1],
                          baddr[j] + bufoff + kofs_b);
                #pragma unroll
                for (int ns = 0; ns < 8; ns++) {
                    mma_bf16(c[0][ns], a[0][0], a[0][1], a[0][2], a[0][3],
                             bfr[ns][0], bfr[ns][1]);
                    mma_bf16(c[1][ns], a[1][0], a[1][1], a[1][2], a[1][3],
                             bfr[ns][0], bfr[ns][1]);
                }
            }

            if (kc < 7) {
                uint32_t* wb = es_u + ((kc + 1) & 1) * ES_WORDS;
                #pragma unroll
                for (int p = 0; p < 4; p++)
                    *reinterpret_cast<uint4*>(&wb[(n0 + 64 * p) * ES_WSTRIDE + 4 * q]) = pf[p];
            }
            __syncthreads();
        }

        // Epilogue: y tile -> bf16 stores + per-thread tile max
        float rmax[4];
        #pragma unroll
        for (int i = 0; i < 4; i++) rmax[i] = -3.4e38f;

        #pragma unroll
        for (int ms = 0; ms < 2; ms++) {
            int r0 = row0 + wm * 32 + ms * 16 + g;
            #pragma unroll
            for (int ns = 0; ns < 8; ns++) {
                rmax[ms * 2]     = fmaxf(rmax[ms * 2],     fmaxf(c[ms][ns][0], c[ms][ns][1]));
                rmax[ms * 2 + 1] = fmaxf(rmax[ms * 2 + 1], fmaxf(c[ms][ns][2], c[ms][ns][3]));
                int col = nb + wn * 64 + ns * 8 + 2 * tig;
                __nv_bfloat162 lo(__float2bfloat16(c[ms][ns][0]), __float2bfloat16(c[ms][ns][1]));
                __nv_bfloat162 hi(__float2bfloat16(c[ms][ns][2]), __float2bfloat16(c[ms][ns][3]));
                *reinterpret_cast<__nv_bfloat162*>(&g_ybf[(size_t)r0 * NCODES + col]) = lo;
                *reinterpret_cast<__nv_bfloat162*>(&g_ybf[(size_t)(r0 + 8) * NCODES + col]) = hi;
            }
        }

        // Reduce tile max across the 16 threads per row; store g_tmax[row][tile]
        float* rm = reinterpret_cast<float*>(es_u);   // E buffers idle here
        #pragma unroll
        for (int ms = 0; ms < 2; ms++)
            #pragma unroll
            for (int half = 0; half < 2; half++) {
                int rl = wm * 32 + ms * 16 + g + half * 8;
                rm[rl * 16 + wn * 4 + tig] = rmax[ms * 2 + half];
            }
        __syncthreads();
        if (tid < 64) {
            float m = -3.4e38f;
            #pragma unroll
            for (int j = 0; j < 16; j++) m = fmaxf(m, rm[tid * 16 + j]);
            g_tmax[(size_t)(row0 + tid) * 64 + (nb >> 8)] = m;
            rowm = fmaxf(rowm, m);
        }
        __syncthreads();
    }

    if (tid < 64) g_rowmax[row0 + tid] = rowm;
}

// ---------------------------------------------------------------------------
// Kernel C: batched bitmask-gated refine (4 rows per block, grid 2048).
// Warp-pair r builds row r's live-tile mask; all 256 threads then scan the
// live tiles of each row. cnt==1 fast path; else fp64 recompute with
// reference rounding d = fl(a - fl(2*fl32(y))), first-index ties.
// a is recomputed on-demand: strictly sequential fp32 sum over s_z in the
// exact reference order (bit-identical to the old a_kernel).
// ---------------------------------------------------------------------------
#define MARGIN 1.2e-4f
#define MAXCAND 64
#define RPB 4

__global__ void refine_kernel(const float* __restrict__ z,
                              const float* __restrict__ e) {
    __shared__ float    s_z[256];
    __shared__ float    s_a;
    __shared__ float    s_d[MAXCAND];
    __shared__ int      s_cand[RPB][MAXCAND];
    __shared__ int      s_cnt[RPB];
    __shared__ uint32_t s_mask[RPB][2];

    const int t = threadIdx.x;
    const int wid = t >> 5, lane = t & 31;
    const int p0 = blockIdx.x * RPB;

    if (t < RPB) s_cnt[t] = 0;

    // Mask build: warp pair (2r, 2r+1) handles row r's 64 tiles
    {
        const int r = wid >> 1, half = wid & 1;
        const int j = half * 32 + lane;
        float tm = g_tmax[(size_t)(p0 + r) * 64 + j];
        float thr = g_rowmax[p0 + r] - MARGIN;
        uint32_t m = __ballot_sync(0xffffffffu, tm > thr);
        if (lane == 0) s_mask[r][half] = m;
    }
    __syncthreads();

    // Candidate scan: all 256 threads, sequential over the 4 rows
    #pragma unroll
    for (int r = 0; r < RPB; r++) {
        const int p = p0 + r;
        const float thr = g_rowmax[p] - MARGIN;
        uint64_t mask = (uint64_t)s_mask[r][0] | ((uint64_t)s_mask[r][1] << 32);
        const __nv_bfloat16* yrow = g_ybf + (size_t)p * NCODES;
        while (mask) {
            int tt = __ffsll((long long)mask) - 1;
            mask &= mask - 1;
            float v = __bfloat162float(yrow[tt * 256 + t]);
            if (v > thr) {
                int slot = atomicAdd(&s_cnt[r], 1);
                if (slot < MAXCAND) s_cand[r][slot] = tt * 256 + t;
            }
        }
    }
    __syncthreads();

    // Resolve each row (block-uniform branching)
    for (int r = 0; r < RPB; r++) {
        const int p = p0 + r;
        const int cnt = min(s_cnt[r], MAXCAND);
        if (cnt <= 1) {                   // fast path: sole candidate = argmin
            if (t == 0) g_idx[p] = s_cand[r][0];
            continue;
        }

        // slow path: load z row, recompute a sequentially, fp64 dots
        const int b = p >> 10, hw = p & 1023;
        s_z[t] = z[(size_t)b * (DIM * 1024) + (size_t)t * 1024 + hw];
        __syncthreads();

        if (t == 0) {
            float acc = 0.f;
            #pragma unroll 8
            for (int c2 = 0; c2 < DIM; c2++)
                acc = __fadd_rn(acc, __fmul_rn(s_z[c2], s_z[c2]));
            s_a = acc;
        }
        __syncthreads();
        const float a = s_a;

        for (int ci = wid; ci < cnt; ci += 8) {
            const float* er = e + (size_t)s_cand[r][ci] * DIM;
            double acc = 0.0;
            #pragma unroll
            for (int j = 0; j < 8; j++) {
                int cc = lane + 32 * j;
                acc += (double)s_z[cc] * (double)er[cc];
            }
            #pragma unroll
            for (int mlt = 16; mlt; mlt >>= 1)
                acc += __shfl_xor_sync(0xffffffffu, acc, mlt);
            if (lane == 0) {
                float y32 = (float)acc;
                s_d[ci] = __fsub_rn(a, __fmul_rn(2.0f, y32));
            }
        }
        __syncthreads();

        if (t == 0) {
            float bd = 3.4e38f; int bn = 0x7fffffff;
            for (int ci = 0; ci < cnt; ci++) {
                float d = s_d[ci]; int n = s_cand[r][ci];
                if (d < bd || (d == bd && n < bn)) { bd = d; bn = n; }
            }
            g_idx[p] = bn;
        }
        __syncthreads();   // protect s_z/s_d before next slow row
    }
}

// ---------------------------------------------------------------------------
// Kernel D: gather + straight-through rounding emulation + partial loss sums.
// ---------------------------------------------------------------------------
__global__ void gather_loss_kernel(const float* __restrict__ z,
                                   const float* __restrict__ e,
                                   float* __restrict__ out) {
    __shared__ float red[256];
    float acc = 0.f;
    for (int i = blockIdx.x * 256 + threadIdx.x; i < ZELEMS; i += 2048 * 256) {
        int bidx = i >> 18;
        int c    = (i >> 10) & 255;
        int hw   = i & 1023;
        int n    = g_idx[(bidx << 10) | hw];
        float v  = e[(size_t)n * DIM + c];
        float zb = z[i];
        float d  = __fsub_rn(v, zb);
        out[i]   = __fadd_rn(zb, d);
        acc += d * d;
    }
    red[threadIdx.x] = acc;
    __syncthreads();
    for (int s = 128; s; s >>= 1) {
        if (threadIdx.x < s) red[threadIdx.x] += red[threadIdx.x + s];
        __syncthreads();
    }
    if (threadIdx.x == 0) g_part[blockIdx.x] = red[0];
}

// ---------------------------------------------------------------------------
// Kernel E: final loss. loss = (BETA + 1) * mean = 2 * sum / ZELEMS
// ---------------------------------------------------------------------------
__global__ void loss_kernel(float* __restrict__ out, int out_size) {
    __shared__ float red[256];
    float acc = 0.f;
    for (int t = threadIdx.x; t < 2048; t += 256) acc += g_part[t];
    red[threadIdx.x] = acc;
    __syncthreads();
    for (int s = 128; s; s >>= 1) {
        if (threadIdx.x < s) red[threadIdx.x] += red[threadIdx.x + s];
        __syncthreads();
    }
    if (threadIdx.x == 0 && out_size > ZELEMS)
        out[ZELEMS] = 2.0f * red[0] / (float)ZELEMS;
}

// ---------------------------------------------------------------------------
extern "C" void kernel_launch(void* const* d_in, const int* in_sizes, int n_in,
                              void* d_out, int out_size) {
    const float* z = (const float*)d_in[0];   // (8,256,32,32) f32
    const float* e = (const float*)d_in[1];   // (16384,256)   f32
    float* out = (float*)d_out;

    cudaFuncSetAttribute(gemm_mma_kernel,
                         cudaFuncAttributeMaxDynamicSharedMemorySize, GEMM_SMEM);

    conv_e_kernel<<<2048, 256>>>(e);
    gemm_mma_kernel<<<PTOT / 64, 256, GEMM_SMEM>>>(z);
    refine_kernel<<<PTOT / RPB, 256>>>(z, e);
    gather_loss_kernel<<<2048, 256>>>(z, e, out);
    loss_kernel<<<1, 256>>>(out, out_size);
}